// round 17
// baseline (speedup 1.0000x reference)
#include <cuda_runtime.h>
#include <cuda_bf16.h>

// feeds: [N=65536, D=512] f32, rep: [N] int32 in [0,8), out: [S=262144, D] f32.
// out row j = feeds[i] where cumsum(rep) first exceeds j; rows >= total are 0.
//
// Pipeline (3 launches, PDL-chained; #2 and #3 overlap their predecessors):
//   1) sums_kernel:   64 blocks -> g_csum[1024] (64-int chunks), g_bsum[64].
//   2) prefix_kernel: 1 block   -> g_bsumx[64] (excl. segment prefix),
//                     g_csumx[1024] (segment-local excl. chunk prefix), g_total.
//   3) scatter_kernel: 128-thr/1-row blocks. Offset = bsumx[seg] + csumx[chunk]
//      + sum(<=15 raw reps) via warp 0 (~18 L2-hot loads). r coalesced 2KB
//      __stcs stores. Tail blocks zero [g_total, S).

#define SEGS 64
#define CHUNKS 1024
__device__ int g_bsum[SEGS];
__device__ int g_csum[CHUNKS];
__device__ int g_bsumx[SEGS];     // exclusive prefix of g_bsum
__device__ int g_csumx[CHUNKS];   // exclusive prefix of g_csum within segment
__device__ int g_total;

__global__ void sums_kernel(const int4* __restrict__ rep4) {
    __shared__ int gs[16];
    const int t = threadIdx.x, b = blockIdx.x;
    const int4 v = __ldg(rep4 + b * 256 + t);
    int s = v.x + v.y + v.z + v.w;
    #pragma unroll
    for (int off = 8; off > 0; off >>= 1)
        s += __shfl_down_sync(0xffffffffu, s, off);
    if ((t & 15) == 0) {
        g_csum[b * 16 + (t >> 4)] = s;
        gs[t >> 4] = s;
    }
    __syncthreads();
    if (t == 0) {
        int tot = 0;
        #pragma unroll
        for (int i = 0; i < 16; i++) tot += gs[i];
        g_bsum[b] = tot;
    }
}

// One block, 1024 threads.
__global__ void prefix_kernel() {
    cudaGridDependencySynchronize();   // g_bsum/g_csum visible
    const int t = threadIdx.x;
    // csumx: thread t sums csum[seg*16 .. t) (<=15 L2-hot loads).
    {
        const int seg = t >> 4;
        int acc = 0;
        for (int i = seg * 16; i < t; i++) acc += __ldg(&g_csum[i]);
        g_csumx[t] = acc;
    }
    // bsumx: warp 0, lanes hold bsum[l] and bsum[l+32]; serial-free scan.
    if (t < 32) {
        const int lane = t;
        int a = __ldg(&g_bsum[lane]);
        int bsec = __ldg(&g_bsum[lane + 32]);
        // inclusive scan of a over 32 lanes
        int inc = a;
        #pragma unroll
        for (int off = 1; off < 32; off <<= 1) {
            int y = __shfl_up_sync(0xffffffffu, inc, off);
            if (lane >= off) inc += y;
        }
        const int sum_lo = __shfl_sync(0xffffffffu, inc, 31);
        int inc2 = bsec;
        #pragma unroll
        for (int off = 1; off < 32; off <<= 1) {
            int y = __shfl_up_sync(0xffffffffu, inc2, off);
            if (lane >= off) inc2 += y;
        }
        g_bsumx[lane] = inc - a;                       // exclusive
        g_bsumx[lane + 32] = sum_lo + inc2 - bsec;     // exclusive
        if (lane == 31) g_total = sum_lo + inc2;       // inclusive total
    }
    cudaTriggerProgrammaticLaunchCompletion();
}

// blocks [0, N): one per source row, 128 threads x float4 = one 2KB row.
// blocks [N, N+TAIL_BLOCKS): grid-stride zero of [g_total*d4, n4).
#define TAIL_BLOCKS 2048
__global__ void scatter_kernel(const float4* __restrict__ feeds,
                               const int* __restrict__ rep,
                               float4* __restrict__ out, int d4, int N,
                               size_t n4) {
    __shared__ int s_val;
    const int b = blockIdx.x;
    const int tid = threadIdx.x;

    if (b < N) {
        const int r = __ldg(rep + b);
        // Prefetch the row (inputs only) while predecessors may still run.
        float4 v;
        if (r > 0) v = feeds[(size_t)b * d4 + tid];
        cudaGridDependencySynchronize();   // bsumx/csumx/total now visible
        if (r == 0) return;

        // Warp 0: offset = bsumx[seg] + csumx[chunk] + sum(raw reps in chunk).
        if (tid < 32) {
            const int seg = b >> 10;
            const int f = b >> 6;
            const int rem = b & 63;
            int acc = 0;
            if (tid == 0) acc = __ldg(&g_bsumx[seg]) + __ldg(&g_csumx[f]);
            const int full = rem >> 2, left = rem & 3;
            if (tid < full) {
                const int4 q = __ldg((const int4*)rep + f * 16 + tid);
                acc += q.x + q.y + q.z + q.w;
            } else if (tid == full && left) {
                const int* p = rep + f * 64 + full * 4;
                acc += p[0] + (left > 1 ? p[1] : 0) + (left > 2 ? p[2] : 0);
            }
            #pragma unroll
            for (int off = 16; off > 0; off >>= 1)
                acc += __shfl_down_sync(0xffffffffu, acc, off);
            if (tid == 0) s_val = acc;
        }
        __syncthreads();

        const int start = s_val;
        float4* dst = out + (size_t)start * d4 + tid;
        for (int k = 0; k < r; k++)
            __stcs(dst + (size_t)k * d4, v);
    } else {
        cudaGridDependencySynchronize();
        const int total = __ldg(&g_total);
        const size_t begin = (size_t)total * d4;
        const size_t tb = b - N;
        const size_t stride = (size_t)TAIL_BLOCKS * blockDim.x;
        const float4 z = make_float4(0.f, 0.f, 0.f, 0.f);
        for (size_t i = begin + tb * blockDim.x + tid; i < n4; i += stride)
            __stcs(out + i, z);
    }
}

static void launch_pdl(void* fn, dim3 grid, dim3 block, void** args) {
    cudaLaunchConfig_t cfg = {};
    cfg.gridDim = grid;
    cfg.blockDim = block;
    cudaLaunchAttribute at[1];
    at[0].id = cudaLaunchAttributeProgrammaticStreamSerialization;
    at[0].val.programmaticStreamSerializationAllowed = 1;
    cfg.attrs = at;
    cfg.numAttrs = 1;
    cudaLaunchKernelExC(&cfg, fn, args);
}

extern "C" void kernel_launch(void* const* d_in, const int* in_sizes, int n_in,
                              void* d_out, int out_size) {
    const float4* feeds = (const float4*)d_in[0];
    const int*    rep   = (const int*)d_in[1];
    float4*       out   = (float4*)d_out;

    const int N = in_sizes[1];                 // 65536 source rows
    const int D = in_sizes[0] / N;             // 512
    const int d4 = D / 4;                      // 128 float4 per row
    const int S = out_size / D;                // 262144 output rows
    const size_t n4 = (size_t)S * d4;

    const int4* rep4 = (const int4*)rep;
    sums_kernel<<<SEGS, 256>>>(rep4);

    {
        void* args[] = {};
        launch_pdl((void*)prefix_kernel, dim3(1), dim3(1024), args);
    }
    {
        int d4v = d4, Nv = N;
        size_t n4v = n4;
        const float4* f = feeds;
        const int* r = rep;
        float4* o = out;
        void* args[] = {(void*)&f, (void*)&r, (void*)&o,
                        (void*)&d4v, (void*)&Nv, (void*)&n4v};
        launch_pdl((void*)scatter_kernel, dim3(N + TAIL_BLOCKS), dim3(d4),
                   args);
    }
}